// round 14
// baseline (speedup 1.0000x reference)
#include <cuda_runtime.h>
#include <cuda_bf16.h>
#include <cstdint>

#define THREADS 256
#define MROWS 64
#define DTS 0.1f

// Pre-swizzled, chunk-blocked bf16 weights. Each 32 KB chunk block is a
// byte-exact image of the SMEM weight buffer (single linear bulk copy).
// granule(n,g) at byte n*256 + ((g^(n&7))<<4), holding 8 bf16.
__device__ __nv_bfloat16 g_w1s[4 * 16384];  // W1^T chunks: [ch][n=h128][u=g*8+j]
__device__ __nv_bfloat16 g_w2s[4 * 16384];  // W2^T chunks: [ch][n=u128][h=g*8+j]

__global__ void prep_kernel(const float* __restrict__ W1,
                            const float* __restrict__ W2) {
    int i = blockIdx.x * blockDim.x + threadIdx.x;   // granule id, 0..16383
    if (i >= 16384) return;
    int arr = i >> 13;          // 0 = W1, 1 = W2
    int idx = i & 8191;
    int ch = idx >> 11;
    int n  = (idx >> 4) & 127;
    int g  = idx & 15;
    uint32_t off = (uint32_t)ch * 32768 + n * 256 + ((g ^ (n & 7)) << 4);
    __nv_bfloat16 v[8];
    if (arr == 0) {
        #pragma unroll
        for (int j = 0; j < 8; j++)
            v[j] = __float2bfloat16_rn(W1[(g * 8 + j) * 512 + ch * 128 + n]);
        *(uint4*)((char*)g_w1s + off) = *(uint4*)v;
    } else {
        #pragma unroll
        for (int j = 0; j < 8; j++)
            v[j] = __float2bfloat16_rn(W2[(ch * 128 + g * 8 + j) * 128 + n]);
        *(uint4*)((char*)g_w2s + off) = *(uint4*)v;
    }
}

// ---------------- PTX helpers ----------------
__device__ __forceinline__ uint32_t smem_u32(const void* p) {
    uint32_t a;
    asm("{ .reg .u64 t; cvta.to.shared.u64 t, %1; cvt.u32.u64 %0, t; }"
        : "=r"(a) : "l"(p));
    return a;
}
__device__ __forceinline__ void ldm_x4(uint32_t* r, uint32_t addr) {
    asm volatile("ldmatrix.sync.aligned.m8n8.x4.shared.b16 {%0,%1,%2,%3}, [%4];"
                 : "=r"(r[0]), "=r"(r[1]), "=r"(r[2]), "=r"(r[3]) : "r"(addr));
}
__device__ __forceinline__ void stm_x4(uint32_t addr, uint32_t r0, uint32_t r1,
                                       uint32_t r2, uint32_t r3) {
    asm volatile("stmatrix.sync.aligned.m8n8.x4.shared.b16 [%0], {%1,%2,%3,%4};"
                 :: "r"(addr), "r"(r0), "r"(r1), "r"(r2), "r"(r3) : "memory");
}
__device__ __forceinline__ void mma16(float* d, const uint32_t* a,
                                      const uint32_t* b) {
    asm volatile(
        "mma.sync.aligned.m16n8k16.row.col.f32.bf16.bf16.f32 "
        "{%0,%1,%2,%3},{%4,%5,%6,%7},{%8,%9},{%0,%1,%2,%3};"
        : "+f"(d[0]), "+f"(d[1]), "+f"(d[2]), "+f"(d[3])
        : "r"(a[0]), "r"(a[1]), "r"(a[2]), "r"(a[3]), "r"(b[0]), "r"(b[1]));
}
__device__ __forceinline__ uint32_t packbf(float lo, float hi) {
    uint32_t r;
    asm("cvt.rn.bf16x2.f32 %0, %1, %2;" : "=r"(r) : "f"(hi), "f"(lo));
    return r;
}
__device__ __forceinline__ void bulk_g2s(uint32_t dst, const void* src,
                                         uint32_t bytes, uint32_t mb) {
    asm volatile(
        "cp.async.bulk.shared::cta.global.mbarrier::complete_tx::bytes "
        "[%0], [%1], %2, [%3];"
        :: "r"(dst), "l"(src), "r"(bytes), "r"(mb) : "memory");
}
#define NAMED_BAR(id) \
    asm volatile("bar.sync %0, 128;" :: "r"(id) : "memory")
#define MBARRIER_INIT(mb, c) \
    asm volatile("mbarrier.init.shared.b64 [%0], %1;" \
                 :: "r"((uint32_t)(mb)), "r"((uint32_t)(c)) : "memory")
#define MBARRIER_EXPECT_TX(mb, n) \
    asm volatile("mbarrier.arrive.expect_tx.shared.b64 _, [%0], %1;" \
                 :: "r"((uint32_t)(mb)), "r"((uint32_t)(n)) : "memory")
#define MBARRIER_ARRIVE(mb) \
    asm volatile("mbarrier.arrive.shared.b64 _, [%0];" \
                 :: "r"((uint32_t)(mb)) : "memory")
#define MBARRIER_WAIT_PARITY(mb, par) do {                                   \
    uint32_t _mb = (uint32_t)(mb), _pa = (uint32_t)(par), _done;             \
    asm volatile("{ .reg .pred p; mbarrier.try_wait.parity.acquire.cta.shared::cta.b64 p, [%1], %2; selp.b32 %0,1,0,p; }" \
                 : "=r"(_done) : "r"(_mb), "r"(_pa) : "memory");             \
    if (!_done) {                                                            \
        asm volatile("{ .reg .pred P1; WL_%=: mbarrier.try_wait.parity.acquire.cta.shared::cta.b64 P1, [%0], %1, 0x989680; @P1 bra.uni WD_%=; bra.uni WL_%=; WD_%=: }" \
                     :: "r"(_mb), "r"(_pa) : "memory");                      \
    } } while (0)

// SMEM layout (bytes). Activation tiles [row][col bf16], 256B rows,
// 16B-granule XOR swizzle: addr(r,c) = r*256 + (((c>>3) ^ (r&7))<<4) + (c&7)*2
#define OFF_E   0            // 16 KB  E (A of GEMM1), 64x128 bf16
#define OFF_H0  16384        // 16 KB  H ping buffer (even chunks)
#define OFF_H1  32768        // 16 KB  H pong buffer (odd chunks)
#define OFF_W1  49152        // 32 KB  W1 chunk [n=h128][k=u128]
#define OFF_W2  81920        // 32 KB  W2 chunk [n=u128][k=h128]
#define OFF_B1  114688       // 512 bf16 (256 x bf16x2)
#define OFF_B2  115712       // 128 bf16 (64 x bf16x2)
#define OFF_MF1 115968       // full-barrier W1
#define OFF_MF2 115976       // full-barrier W2
#define OFF_MC1 115984       // consumed-barrier W1 (8 warp arrivals)
#define OFF_MC2 115992       // consumed-barrier W2
#define SMEM_TOTAL 116096

__global__ void __launch_bounds__(THREADS, 2)
rk4_kernel(const float* __restrict__ x0, const float* __restrict__ b1g,
           const float* __restrict__ b2g, float* __restrict__ xout) {
    extern __shared__ unsigned char smem[];
    const uint32_t sb = smem_u32(smem);
    __nv_bfloat162* sB1 = (__nv_bfloat162*)(smem + OFF_B1);  // 256 pairs
    __nv_bfloat162* sB2 = (__nv_bfloat162*)(smem + OFF_B2);  // 64 pairs

    const int tid  = threadIdx.x;
    const int lane = tid & 31;
    const int wid  = tid >> 5;     // 0..7
    const int qr   = lane >> 2;
    const int qc   = lane & 3;
    const int wm   = wid >> 2;     // 0..1  M strip (32 rows); warps 0-3 / 4-7
    const int wn   = wid & 3;      // 0..3  N strip (32 cols)
    const int barid = 1 + wm;      // named barrier per wm-group

    if (tid == 0) {
        MBARRIER_INIT(sb + OFF_MF1, 1);
        MBARRIER_INIT(sb + OFF_MF2, 1);
        MBARRIER_INIT(sb + OFF_MC1, 8);
        MBARRIER_INIT(sb + OFF_MC2, 8);
    }
    // biases stored as bf16x2 pairs (b1/b2 are zeros in this dataset;
    // general case loses <=bf16 eps on bias only)
    {
        float v0 = b1g[2 * tid], v1 = b1g[2 * tid + 1];
        *(uint32_t*)&sB1[tid] = packbf(v0, v1);
        if (tid < 64) {
            float w0 = b2g[2 * tid], w1 = b2g[2 * tid + 1];
            *(uint32_t*)&sB2[tid] = packbf(w0, w1);
        }
    }

    // ---- init: x0 -> xout (fp32 state) and sE (bf16, swizzled) ----
    const float* xg = x0   + (size_t)blockIdx.x * (MROWS * 128);
    float*       xo = xout + (size_t)blockIdx.x * (MROWS * 128);
    for (int i = tid; i < MROWS * 64; i += THREADS) {   // one bf16x2 each
        int r = i >> 6, c = (i & 63) << 1;
        float2 v = *(const float2*)(xg + r * 128 + c);
        *(float2*)(xo + r * 128 + c) = v;
        *(uint32_t*)(smem + OFF_E + r * 256 + (((c >> 3) ^ (r & 7)) << 4) +
                     (c & 7) * 2) = packbf(v.x, v.y);
    }
    __syncthreads();   // mbarriers initialized, sE/biases written

    if (tid == 0) {
        MBARRIER_EXPECT_TX(sb + OFF_MF1, 32768);
        bulk_g2s(sb + OFF_W1, g_w1s, 32768, sb + OFF_MF1);
        MBARRIER_EXPECT_TX(sb + OFF_MF2, 32768);
        bulk_g2s(sb + OFF_W2, g_w2s, 32768, sb + OFF_MF2);
    }

    // ldmatrix lane address components
    const int arow0 = wm * 32 + ((lane >> 3) & 1) * 8 + (lane & 7);  // +mi*16
    const int asel  = lane >> 4;            // k8-half for A
    const int brow0 = ((lane >> 4) << 3) + (lane & 7);               // +pr*16
    const int bsel  = (lane >> 3) & 1;      // k8-half for B

    // stmatrix lane address: matrix g = lane>>3 -> {mi = g>>1, rh = g&1}
    const int srow = wm * 32 + ((lane >> 4) & 1) * 16 + ((lane >> 3) & 1) * 8 +
                     (lane & 7);
    const uint32_t srow_base = (uint32_t)srow * 256;
    const int s7 = srow & 7;

    float acc[32];
    #pragma unroll
    for (int i = 0; i < 32; i++) acc[i] = 0.0f;

    int pf1 = 0, pf2 = 0, pc1 = 0, pc2 = 0;   // mbarrier phase parities

    #pragma unroll 1
    for (int ev = 0; ev < 80; ev++) {
        const int stage = ev & 3;
        const float ws = (stage == 0 || stage == 3) ? 1.0f : 2.0f;
        const float cs = (stage == 2) ? DTS : 0.5f * DTS;

        float out[32];
        #pragma unroll
        for (int i = 0; i < 32; i++) out[i] = 0.0f;

        #pragma unroll 1
        for (int ch = 0; ch < 4; ch++) {
            const bool last = (ev == 79 && ch == 3);
            const uint32_t offH = (ch & 1) ? OFF_H1 : OFF_H0;

            // wait W1(ch) ready
            MBARRIER_WAIT_PARITY(sb + OFF_MF1, pf1); pf1 ^= 1;

            // ---- GEMM1: h1 = E(64x128) @ W1c^T, warp tile M32 x N32 ----
            float h1[32];
            #pragma unroll
            for (int i = 0; i < 32; i++) h1[i] = 0.0f;
            #pragma unroll
            for (int k16 = 0; k16 < 8; k16++) {
                uint32_t a[2][4], b[2][4];
                #pragma unroll
                for (int mi = 0; mi < 2; mi++) {
                    int r = arow0 + mi * 16;
                    ldm_x4(a[mi], sb + OFF_E + r * 256 +
                                  (((2 * k16 + asel) ^ (r & 7)) << 4));
                }
                #pragma unroll
                for (int pr = 0; pr < 2; pr++) {
                    int n = wn * 32 + pr * 16 + brow0;
                    ldm_x4(b[pr], sb + OFF_W1 + n * 256 +
                                  (((2 * k16 + bsel) ^ (n & 7)) << 4));
                }
                #pragma unroll
                for (int mi = 0; mi < 2; mi++)
                    #pragma unroll
                    for (int pr = 0; pr < 2; pr++)
                        #pragma unroll
                        for (int j = 0; j < 2; j++)
                            mma16(h1 + (mi * 4 + pr * 2 + j) * 4,
                                  a[mi], &b[pr][2 * j]);
            }
            if (lane == 0) MBARRIER_ARRIVE(sb + OFF_MC1);  // W1(ch) consumed

            // ---- epilogue1: bias + relu -> H[ch&1] via stmatrix.x4 ----
            #pragma unroll
            for (int ni = 0; ni < 4; ni++) {
                const int col = wn * 32 + ni * 8 + 2 * qc;
                const __nv_bfloat162 bp = sB1[(ch * 128 + col) >> 1];
                const float bb0 = __bfloat162float(bp.x);
                const float bb1 = __bfloat162float(bp.y);
                const int q0 = ni * 4;        // mi = 0
                const int q1 = (4 + ni) * 4;  // mi = 1
                uint32_t m0 = packbf(fmaxf(h1[q0 + 0] + bb0, 0.0f),
                                     fmaxf(h1[q0 + 1] + bb1, 0.0f));
                uint32_t m1 = packbf(fmaxf(h1[q0 + 2] + bb0, 0.0f),
                                     fmaxf(h1[q0 + 3] + bb1, 0.0f));
                uint32_t m2 = packbf(fmaxf(h1[q1 + 0] + bb0, 0.0f),
                                     fmaxf(h1[q1 + 1] + bb1, 0.0f));
                uint32_t m3 = packbf(fmaxf(h1[q1 + 2] + bb0, 0.0f),
                                     fmaxf(h1[q1 + 3] + bb1, 0.0f));
                const int g8 = wn * 4 + ni;
                stm_x4(sb + offH + srow_base + ((g8 ^ s7) << 4),
                       m0, m1, m2, m3);
            }
            NAMED_BAR(barid);   // H[ch&1] strip visible within wm-group
            // (also proves all group warps finished G2(ch-1): safe to
            //  overwrite H[(ch+1)&1] next chunk without a second barrier)

            // reissue W1(next chunk) once all 8 warps consumed it
            if (!last) {
                if (tid == 0) {
                    MBARRIER_WAIT_PARITY(sb + OFF_MC1, pc1);
                    MBARRIER_EXPECT_TX(sb + OFF_MF1, 32768);
                    bulk_g2s(sb + OFF_W1,
                             (const char*)g_w1s + ((ch + 1) & 3) * 32768,
                             32768, sb + OFF_MF1);
                }
                pc1 ^= 1;
            }

            // wait W2(ch) ready
            MBARRIER_WAIT_PARITY(sb + OFF_MF2, pf2); pf2 ^= 1;

            // ---- GEMM2: out += H[ch&1](64x128) @ W2c^T ----
            #pragma unroll
            for (int k16 = 0; k16 < 8; k16++) {
                uint32_t a[2][4], b[2][4];
                #pragma unroll
                for (int mi = 0; mi < 2; mi++) {
                    int r = arow0 + mi * 16;
                    ldm_x4(a[mi], sb + offH + r * 256 +
                                  (((2 * k16 + asel) ^ (r & 7)) << 4));
                }
                #pragma unroll
                for (int pr = 0; pr < 2; pr++) {
                    int n = wn * 32 + pr * 16 + brow0;
                    ldm_x4(b[pr], sb + OFF_W2 + n * 256 +
                                  (((2 * k16 + bsel) ^ (n & 7)) << 4));
                }
                #pragma unroll
                for (int mi = 0; mi < 2; mi++)
                    #pragma unroll
                    for (int pr = 0; pr < 2; pr++)
                        #pragma unroll
                        for (int j = 0; j < 2; j++)
                            mma16(out + (mi * 4 + pr * 2 + j) * 4,
                                  a[mi], &b[pr][2 * j]);
            }
            if (lane == 0) MBARRIER_ARRIVE(sb + OFF_MC2);  // W2(ch) consumed

            // reissue W2(next chunk)
            if (!last) {
                if (tid == 0) {
                    MBARRIER_WAIT_PARITY(sb + OFF_MC2, pc2);
                    MBARRIER_EXPECT_TX(sb + OFF_MF2, 32768);
                    bulk_g2s(sb + OFF_W2,
                             (const char*)g_w2s + ((ch + 1) & 3) * 32768,
                             32768, sb + OFF_MF2);
                }
                pc2 ^= 1;
            }
        }  // chunks

        // ---- RK4 stage epilogue (x in xout; E written via stmatrix) ----
        #pragma unroll
        for (int ni = 0; ni < 4; ni++) {
            const int col = wn * 32 + ni * 8 + 2 * qc;
            const __nv_bfloat162 b2p = sB2[col >> 1];
            const float b2v0 = __bfloat162float(b2p.x);
            const float b2v1 = __bfloat162float(b2p.y);
            uint32_t m[4];
            #pragma unroll
            for (int mi = 0; mi < 2; mi++) {
                const int q   = (mi * 4 + ni) * 4;
                const int row = wm * 32 + mi * 16 + qr;
                float2* xp0 = (float2*)(xo + row * 128 + col);
                float2* xp1 = (float2*)(xo + (row + 8) * 128 + col);
                float2 xv0 = *xp0, xv1 = *xp1;
                float k0 = out[q + 0] + b2v0;
                float k1 = out[q + 1] + b2v1;
                float k2 = out[q + 2] + b2v0;
                float k3 = out[q + 3] + b2v1;
                acc[q + 0] += ws * k0; acc[q + 1] += ws * k1;
                acc[q + 2] += ws * k2; acc[q + 3] += ws * k3;
                if (stage < 3) {
                    m[mi * 2 + 0] = packbf(xv0.x + cs * k0, xv0.y + cs * k1);
                    m[mi * 2 + 1] = packbf(xv1.x + cs * k2, xv1.y + cs * k3);
                } else {
                    float n0 = xv0.x + (DTS / 6.0f) * acc[q + 0];
                    float n1 = xv0.y + (DTS / 6.0f) * acc[q + 1];
                    float n2 = xv1.x + (DTS / 6.0f) * acc[q + 2];
                    float n3 = xv1.y + (DTS / 6.0f) * acc[q + 3];
                    *xp0 = make_float2(n0, n1);
                    *xp1 = make_float2(n2, n3);
                    acc[q + 0] = acc[q + 1] = acc[q + 2] = acc[q + 3] = 0.0f;
                    m[mi * 2 + 0] = packbf(n0, n1);
                    m[mi * 2 + 1] = packbf(n2, n3);
                }
            }
            const int g8 = wn * 4 + ni;
            stm_x4(sb + OFF_E + srow_base + ((g8 ^ s7) << 4),
                   m[0], m[1], m[2], m[3]);
        }
        NAMED_BAR(barid);   // E strip visible before next eval's GEMM1
    }  // evals
}

extern "C" void kernel_launch(void* const* d_in, const int* in_sizes, int n_in,
                              void* d_out, int out_size) {
    const float* x0 = (const float*)d_in[0];
    const float* W1 = (const float*)d_in[1];
    const float* b1 = (const float*)d_in[2];
    const float* W2 = (const float*)d_in[3];
    const float* b2 = (const float*)d_in[4];
    float* out = (float*)d_out;

    static bool configured = false;
    if (!configured) {
        cudaFuncSetAttribute(rk4_kernel,
                             cudaFuncAttributeMaxDynamicSharedMemorySize,
                             SMEM_TOTAL);
        configured = true;
    }

    prep_kernel<<<64, 256>>>(W1, W2);
    rk4_kernel<<<65536 / MROWS, THREADS, SMEM_TOTAL>>>(x0, b1, b2, out);
}

// round 16
// speedup vs baseline: 1.0947x; 1.0947x over previous
#include <cuda_runtime.h>
#include <cuda_bf16.h>
#include <cstdint>

#define THREADS 256
#define MROWS 64
#define DTS 0.1f

// W1 chunk blocks: 32768 B pre-swizzled weights + 256 B bf16 bias tail
// (b1[ch*128 .. ch*128+127]).  One 33024-B bulk copy delivers both.
// Weight granule(n,g) at byte ch*33024 + n*256 + ((g^(n&7))<<4), 8 bf16 each.
__device__ __align__(16) unsigned char g_w1s[4 * 33024];
// W2 chunk blocks: plain 32768 B pre-swizzled images (as before).
__device__ __nv_bfloat16 g_w2s[4 * 16384];

__global__ void prep_kernel(const float* __restrict__ W1,
                            const float* __restrict__ b1,
                            const float* __restrict__ W2) {
    int i = blockIdx.x * blockDim.x + threadIdx.x;
    if (i < 16384) {
        int arr = i >> 13;          // 0 = W1 weights, 1 = W2 weights
        int idx = i & 8191;
        int ch = idx >> 11;
        int n  = (idx >> 4) & 127;
        int g  = idx & 15;
        __nv_bfloat16 v[8];
        if (arr == 0) {
            #pragma unroll
            for (int j = 0; j < 8; j++)
                v[j] = __float2bfloat16_rn(W1[(g * 8 + j) * 512 + ch * 128 + n]);
            uint32_t off = (uint32_t)ch * 33024 + n * 256 + ((g ^ (n & 7)) << 4);
            *(uint4*)(g_w1s + off) = *(uint4*)v;
        } else {
            #pragma unroll
            for (int j = 0; j < 8; j++)
                v[j] = __float2bfloat16_rn(W2[(ch * 128 + g * 8 + j) * 128 + n]);
            uint32_t off = (uint32_t)ch * 32768 + n * 256 + ((g ^ (n & 7)) << 4);
            *(uint4*)((char*)g_w2s + off) = *(uint4*)v;
        }
    } else if (i < 16384 + 64) {
        // bias tails: 4 chunks x 16 granules of 8 bf16
        int j  = i - 16384;
        int ch = j >> 4;
        int g  = j & 15;
        __nv_bfloat16 v[8];
        #pragma unroll
        for (int k = 0; k < 8; k++)
            v[k] = __float2bfloat16_rn(b1[ch * 128 + g * 8 + k]);
        *(uint4*)(g_w1s + (uint32_t)ch * 33024 + 32768 + g * 16) = *(uint4*)v;
    }
}

// ---------------- PTX helpers ----------------
__device__ __forceinline__ uint32_t smem_u32(const void* p) {
    uint32_t a;
    asm("{ .reg .u64 t; cvta.to.shared.u64 t, %1; cvt.u32.u64 %0, t; }"
        : "=r"(a) : "l"(p));
    return a;
}
__device__ __forceinline__ void ldm_x4(uint32_t* r, uint32_t addr) {
    asm volatile("ldmatrix.sync.aligned.m8n8.x4.shared.b16 {%0,%1,%2,%3}, [%4];"
                 : "=r"(r[0]), "=r"(r[1]), "=r"(r[2]), "=r"(r[3]) : "r"(addr));
}
__device__ __forceinline__ void stm_x4(uint32_t addr, uint32_t r0, uint32_t r1,
                                       uint32_t r2, uint32_t r3) {
    asm volatile("stmatrix.sync.aligned.m8n8.x4.shared.b16 [%0], {%1,%2,%3,%4};"
                 :: "r"(addr), "r"(r0), "r"(r1), "r"(r2), "r"(r3) : "memory");
}
__device__ __forceinline__ void mma16(float* d, const uint32_t* a,
                                      const uint32_t* b) {
    asm volatile(
        "mma.sync.aligned.m16n8k16.row.col.f32.bf16.bf16.f32 "
        "{%0,%1,%2,%3},{%4,%5,%6,%7},{%8,%9},{%0,%1,%2,%3};"
        : "+f"(d[0]), "+f"(d[1]), "+f"(d[2]), "+f"(d[3])
        : "r"(a[0]), "r"(a[1]), "r"(a[2]), "r"(a[3]), "r"(b[0]), "r"(b[1]));
}
__device__ __forceinline__ uint32_t packbf(float lo, float hi) {
    uint32_t r;
    asm("cvt.rn.bf16x2.f32 %0, %1, %2;" : "=r"(r) : "f"(hi), "f"(lo));
    return r;
}
__device__ __forceinline__ void bulk_g2s(uint32_t dst, const void* src,
                                         uint32_t bytes, uint32_t mb) {
    asm volatile(
        "cp.async.bulk.shared::cta.global.mbarrier::complete_tx::bytes "
        "[%0], [%1], %2, [%3];"
        :: "r"(dst), "l"(src), "r"(bytes), "r"(mb) : "memory");
}
#define NAMED_BAR(id) \
    asm volatile("bar.sync %0, 128;" :: "r"(id) : "memory")
#define MBARRIER_INIT(mb, c) \
    asm volatile("mbarrier.init.shared.b64 [%0], %1;" \
                 :: "r"((uint32_t)(mb)), "r"((uint32_t)(c)) : "memory")
#define MBARRIER_EXPECT_TX(mb, n) \
    asm volatile("mbarrier.arrive.expect_tx.shared.b64 _, [%0], %1;" \
                 :: "r"((uint32_t)(mb)), "r"((uint32_t)(n)) : "memory")
#define MBARRIER_ARRIVE(mb) \
    asm volatile("mbarrier.arrive.shared.b64 _, [%0];" \
                 :: "r"((uint32_t)(mb)) : "memory")
#define MBARRIER_WAIT_PARITY(mb, par) do {                                   \
    uint32_t _mb = (uint32_t)(mb), _pa = (uint32_t)(par), _done;             \
    asm volatile("{ .reg .pred p; mbarrier.try_wait.parity.acquire.cta.shared::cta.b64 p, [%1], %2; selp.b32 %0,1,0,p; }" \
                 : "=r"(_done) : "r"(_mb), "r"(_pa) : "memory");             \
    if (!_done) {                                                            \
        asm volatile("{ .reg .pred P1; WL_%=: mbarrier.try_wait.parity.acquire.cta.shared::cta.b64 P1, [%0], %1, 0x989680; @P1 bra.uni WD_%=; bra.uni WL_%=; WD_%=: }" \
                     :: "r"(_mb), "r"(_pa) : "memory");                      \
    } } while (0)

// SMEM layout (bytes).  S = 115328 <= 115712 -> 2 CTAs/SM.
#define OFF_E   0            // 16 KB  E (A of GEMM1), 64x128 bf16
#define OFF_H0  16384        // 16 KB  H ping buffer (even chunks)
#define OFF_H1  32768        // 16 KB  H pong buffer (odd chunks)
#define OFF_W1  49152        // 33024 B: W1 chunk + 256 B bias tail
#define OFF_W2  82176        // 32 KB  W2 chunk [n=u128][k=h128]
#define OFF_B2  114944       // 256 B  b2 as bf16x2
#define OFF_MF1 115200       // full-barrier W1
#define OFF_MF2 115208       // full-barrier W2
#define OFF_MC1 115216       // consumed-barrier W1 (8 warp arrivals)
#define OFF_MC2 115224       // consumed-barrier W2
#define SMEM_TOTAL 115328

__global__ void __launch_bounds__(THREADS, 2)
rk4_kernel(const float* __restrict__ x0, const float* __restrict__ b2g,
           float* __restrict__ xout) {
    extern __shared__ unsigned char smem[];
    const uint32_t sb = smem_u32(smem);
    __nv_bfloat162* sB2 = (__nv_bfloat162*)(smem + OFF_B2);  // 64 pairs

    const int tid  = threadIdx.x;
    const int lane = tid & 31;
    const int wid  = tid >> 5;     // 0..7
    const int qr   = lane >> 2;
    const int qc   = lane & 3;
    const int wm   = wid >> 2;     // 0..1  M strip (32 rows); warps 0-3 / 4-7
    const int wn   = wid & 3;      // 0..3  N strip (32 cols)
    const int barid = 1 + wm;      // named barrier per wm-group

    if (tid == 0) {
        MBARRIER_INIT(sb + OFF_MF1, 1);
        MBARRIER_INIT(sb + OFF_MF2, 1);
        MBARRIER_INIT(sb + OFF_MC1, 8);
        MBARRIER_INIT(sb + OFF_MC2, 8);
    }
    if (tid < 64) {
        float w0 = b2g[2 * tid], w1 = b2g[2 * tid + 1];
        *(uint32_t*)&sB2[tid] = packbf(w0, w1);
    }

    // ---- init: x0 -> xout (fp32 state) and sE (bf16, swizzled) ----
    const float* xg = x0   + (size_t)blockIdx.x * (MROWS * 128);
    float*       xo = xout + (size_t)blockIdx.x * (MROWS * 128);
    for (int i = tid; i < MROWS * 64; i += THREADS) {   // one bf16x2 each
        int r = i >> 6, c = (i & 63) << 1;
        float2 v = *(const float2*)(xg + r * 128 + c);
        *(float2*)(xo + r * 128 + c) = v;
        *(uint32_t*)(smem + OFF_E + r * 256 + (((c >> 3) ^ (r & 7)) << 4) +
                     (c & 7) * 2) = packbf(v.x, v.y);
    }
    __syncthreads();   // mbarriers initialized, sE/B2 written

    if (tid == 0) {
        MBARRIER_EXPECT_TX(sb + OFF_MF1, 33024);
        bulk_g2s(sb + OFF_W1, g_w1s, 33024, sb + OFF_MF1);
        MBARRIER_EXPECT_TX(sb + OFF_MF2, 32768);
        bulk_g2s(sb + OFF_W2, g_w2s, 32768, sb + OFF_MF2);
    }

    // ldmatrix lane address components
    const int arow0 = wm * 32 + ((lane >> 3) & 1) * 8 + (lane & 7);  // +mi*16
    const int asel  = lane >> 4;            // k8-half for A
    const int brow0 = ((lane >> 4) << 3) + (lane & 7);               // +pr*16
    const int bsel  = (lane >> 3) & 1;      // k8-half for B

    // stmatrix lane address: matrix g = lane>>3 -> {mi = g>>1, rh = g&1}
    const int srow = wm * 32 + ((lane >> 4) & 1) * 16 + ((lane >> 3) & 1) * 8 +
                     (lane & 7);
    const uint32_t srow_base = (uint32_t)srow * 256;
    const int s7 = srow & 7;

    float acc[32];
    #pragma unroll
    for (int i = 0; i < 32; i++) acc[i] = 0.0f;

    int pf1 = 0, pf2 = 0, pc1 = 0, pc2 = 0;   // mbarrier phase parities

    #pragma unroll 1
    for (int ev = 0; ev < 80; ev++) {
        const int stage = ev & 3;
        const float ws = (stage == 0 || stage == 3) ? 1.0f : 2.0f;
        const float cs = (stage == 2) ? DTS : 0.5f * DTS;

        float out[32];
        #pragma unroll
        for (int i = 0; i < 32; i++) out[i] = 0.0f;

        #pragma unroll 1
        for (int ch = 0; ch < 4; ch++) {
            const bool last = (ev == 79 && ch == 3);
            const uint32_t offH = (ch & 1) ? OFF_H1 : OFF_H0;

            // wait W1(ch) ready (weights + this chunk's bias tail)
            MBARRIER_WAIT_PARITY(sb + OFF_MF1, pf1); pf1 ^= 1;

            // ---- GEMM1: h1 = E(64x128) @ W1c^T, warp tile M32 x N32 ----
            float h1[32];
            #pragma unroll
            for (int i = 0; i < 32; i++) h1[i] = 0.0f;
            #pragma unroll
            for (int k16 = 0; k16 < 8; k16++) {
                uint32_t a[2][4], b[2][4];
                #pragma unroll
                for (int mi = 0; mi < 2; mi++) {
                    int r = arow0 + mi * 16;
                    ldm_x4(a[mi], sb + OFF_E + r * 256 +
                                  (((2 * k16 + asel) ^ (r & 7)) << 4));
                }
                #pragma unroll
                for (int pr = 0; pr < 2; pr++) {
                    int n = wn * 32 + pr * 16 + brow0;
                    ldm_x4(b[pr], sb + OFF_W1 + n * 256 +
                                  (((2 * k16 + bsel) ^ (n & 7)) << 4));
                }
                #pragma unroll
                for (int mi = 0; mi < 2; mi++)
                    #pragma unroll
                    for (int pr = 0; pr < 2; pr++)
                        #pragma unroll
                        for (int j = 0; j < 2; j++)
                            mma16(h1 + (mi * 4 + pr * 2 + j) * 4,
                                  a[mi], &b[pr][2 * j]);
            }

            // ---- epilogue1: bias (from W1 tail) + relu -> H[ch&1] ----
            #pragma unroll
            for (int ni = 0; ni < 4; ni++) {
                const int col = wn * 32 + ni * 8 + 2 * qc;
                const __nv_bfloat162 bp =
                    *(__nv_bfloat162*)(smem + OFF_W1 + 32768 + col * 2);
                const float bb0 = __bfloat162float(bp.x);
                const float bb1 = __bfloat162float(bp.y);
                const int q0 = ni * 4;        // mi = 0
                const int q1 = (4 + ni) * 4;  // mi = 1
                uint32_t m0 = packbf(fmaxf(h1[q0 + 0] + bb0, 0.0f),
                                     fmaxf(h1[q0 + 1] + bb1, 0.0f));
                uint32_t m1 = packbf(fmaxf(h1[q0 + 2] + bb0, 0.0f),
                                     fmaxf(h1[q0 + 3] + bb1, 0.0f));
                uint32_t m2 = packbf(fmaxf(h1[q1 + 0] + bb0, 0.0f),
                                     fmaxf(h1[q1 + 1] + bb1, 0.0f));
                uint32_t m3 = packbf(fmaxf(h1[q1 + 2] + bb0, 0.0f),
                                     fmaxf(h1[q1 + 3] + bb1, 0.0f));
                const int g8 = wn * 4 + ni;
                stm_x4(sb + offH + srow_base + ((g8 ^ s7) << 4),
                       m0, m1, m2, m3);
            }
            // W1(ch) fully consumed (weights by G1, bias by epilogue1)
            if (lane == 0) MBARRIER_ARRIVE(sb + OFF_MC1);
            NAMED_BAR(barid);   // H[ch&1] strip visible within wm-group
            // (also proves all group warps finished G2(ch-1): safe to
            //  overwrite H[(ch+1)&1] next chunk without a second barrier)

            // reissue W1(next chunk) once all 8 warps consumed it
            if (!last) {
                if (tid == 0) {
                    MBARRIER_WAIT_PARITY(sb + OFF_MC1, pc1);
                    MBARRIER_EXPECT_TX(sb + OFF_MF1, 33024);
                    bulk_g2s(sb + OFF_W1,
                             g_w1s + (uint32_t)((ch + 1) & 3) * 33024,
                             33024, sb + OFF_MF1);
                }
                pc1 ^= 1;
            }

            // wait W2(ch) ready
            MBARRIER_WAIT_PARITY(sb + OFF_MF2, pf2); pf2 ^= 1;

            // ---- GEMM2: out += H[ch&1](64x128) @ W2c^T ----
            #pragma unroll
            for (int k16 = 0; k16 < 8; k16++) {
                uint32_t a[2][4], b[2][4];
                #pragma unroll
                for (int mi = 0; mi < 2; mi++) {
                    int r = arow0 + mi * 16;
                    ldm_x4(a[mi], sb + offH + r * 256 +
                                  (((2 * k16 + asel) ^ (r & 7)) << 4));
                }
                #pragma unroll
                for (int pr = 0; pr < 2; pr++) {
                    int n = wn * 32 + pr * 16 + brow0;
                    ldm_x4(b[pr], sb + OFF_W2 + n * 256 +
                                  (((2 * k16 + bsel) ^ (n & 7)) << 4));
                }
                #pragma unroll
                for (int mi = 0; mi < 2; mi++)
                    #pragma unroll
                    for (int pr = 0; pr < 2; pr++)
                        #pragma unroll
                        for (int j = 0; j < 2; j++)
                            mma16(out + (mi * 4 + pr * 2 + j) * 4,
                                  a[mi], &b[pr][2 * j]);
            }
            if (lane == 0) MBARRIER_ARRIVE(sb + OFF_MC2);  // W2(ch) consumed

            // reissue W2(next chunk)
            if (!last) {
                if (tid == 0) {
                    MBARRIER_WAIT_PARITY(sb + OFF_MC2, pc2);
                    MBARRIER_EXPECT_TX(sb + OFF_MF2, 32768);
                    bulk_g2s(sb + OFF_W2,
                             (const char*)g_w2s + ((ch + 1) & 3) * 32768,
                             32768, sb + OFF_MF2);
                }
                pc2 ^= 1;
            }
        }  // chunks

        // ---- RK4 stage epilogue (x in xout; E written via stmatrix) ----
        #pragma unroll
        for (int ni = 0; ni < 4; ni++) {
            const int col = wn * 32 + ni * 8 + 2 * qc;
            const __nv_bfloat162 b2p = sB2[col >> 1];
            const float b2v0 = __bfloat162float(b2p.x);
            const float b2v1 = __bfloat162float(b2p.y);
            uint32_t m[4];
            #pragma unroll
            for (int mi = 0; mi < 2; mi++) {
                const int q   = (mi * 4 + ni) * 4;
                const int row = wm * 32 + mi * 16 + qr;
                float2* xp0 = (float2*)(xo + row * 128 + col);
                float2* xp1 = (float2*)(xo + (row + 8) * 128 + col);
                float2 xv0 = *xp0, xv1 = *xp1;
                float k0 = out[q + 0] + b2v0;
                float k1 = out[q + 1] + b2v1;
                float k2 = out[q + 2] + b2v0;
                float k3 = out[q + 3] + b2v1;
                acc[q + 0] += ws * k0; acc[q + 1] += ws * k1;
                acc[q + 2] += ws * k2; acc[q + 3] += ws * k3;
                if (stage < 3) {
                    m[mi * 2 + 0] = packbf(xv0.x + cs * k0, xv0.y + cs * k1);
                    m[mi * 2 + 1] = packbf(xv1.x + cs * k2, xv1.y + cs * k3);
                } else {
                    float n0 = xv0.x + (DTS / 6.0f) * acc[q + 0];
                    float n1 = xv0.y + (DTS / 6.0f) * acc[q + 1];
                    float n2 = xv1.x + (DTS / 6.0f) * acc[q + 2];
                    float n3 = xv1.y + (DTS / 6.0f) * acc[q + 3];
                    *xp0 = make_float2(n0, n1);
                    *xp1 = make_float2(n2, n3);
                    acc[q + 0] = acc[q + 1] = acc[q + 2] = acc[q + 3] = 0.0f;
                    m[mi * 2 + 0] = packbf(n0, n1);
                    m[mi * 2 + 1] = packbf(n2, n3);
                }
            }
            const int g8 = wn * 4 + ni;
            stm_x4(sb + OFF_E + srow_base + ((g8 ^ s7) << 4),
                   m[0], m[1], m[2], m[3]);
        }
        NAMED_BAR(barid);   // E strip visible before next eval's GEMM1
    }  // evals
}

extern "C" void kernel_launch(void* const* d_in, const int* in_sizes, int n_in,
                              void* d_out, int out_size) {
    const float* x0 = (const float*)d_in[0];
    const float* W1 = (const float*)d_in[1];
    const float* b1 = (const float*)d_in[2];
    const float* W2 = (const float*)d_in[3];
    const float* b2 = (const float*)d_in[4];
    float* out = (float*)d_out;

    static bool configured = false;
    if (!configured) {
        cudaFuncSetAttribute(rk4_kernel,
                             cudaFuncAttributeMaxDynamicSharedMemorySize,
                             SMEM_TOTAL);
        configured = true;
    }

    prep_kernel<<<65, 256>>>(W1, b1, W2);
    rk4_kernel<<<65536 / MROWS, THREADS, SMEM_TOTAL>>>(x0, b2, out);
}

// round 17
// speedup vs baseline: 1.1033x; 1.0079x over previous
#include <cuda_runtime.h>
#include <cuda_bf16.h>
#include <cstdint>

#define THREADS 256
#define MROWS 64
#define DTS 0.1f

// Pre-swizzled, chunk-blocked bf16 weights. Each 32 KB chunk block is a
// byte-exact image of the SMEM weight buffer (single linear bulk copy).
// granule(n,g) at byte n*256 + ((g^(n&7))<<4), holding 8 bf16.
__device__ __nv_bfloat16 g_w1s[4 * 16384];  // W1^T chunks: [ch][n=h128][u=g*8+j]
__device__ __nv_bfloat16 g_w2s[4 * 16384];  // W2^T chunks: [ch][n=u128][h=g*8+j]

__global__ void prep_kernel(const float* __restrict__ W1,
                            const float* __restrict__ W2) {
    int i = blockIdx.x * blockDim.x + threadIdx.x;   // granule id, 0..16383
    if (i >= 16384) return;
    int arr = i >> 13;          // 0 = W1, 1 = W2
    int idx = i & 8191;
    int ch = idx >> 11;
    int n  = (idx >> 4) & 127;
    int g  = idx & 15;
    uint32_t off = (uint32_t)ch * 32768 + n * 256 + ((g ^ (n & 7)) << 4);
    __nv_bfloat16 v[8];
    if (arr == 0) {
        #pragma unroll
        for (int j = 0; j < 8; j++)
            v[j] = __float2bfloat16_rn(W1[(g * 8 + j) * 512 + ch * 128 + n]);
        *(uint4*)((char*)g_w1s + off) = *(uint4*)v;
    } else {
        #pragma unroll
        for (int j = 0; j < 8; j++)
            v[j] = __float2bfloat16_rn(W2[(ch * 128 + g * 8 + j) * 128 + n]);
        *(uint4*)((char*)g_w2s + off) = *(uint4*)v;
    }
}

// ---------------- PTX helpers ----------------
__device__ __forceinline__ uint32_t smem_u32(const void* p) {
    uint32_t a;
    asm("{ .reg .u64 t; cvta.to.shared.u64 t, %1; cvt.u32.u64 %0, t; }"
        : "=r"(a) : "l"(p));
    return a;
}
__device__ __forceinline__ void ldm_x4(uint32_t* r, uint32_t addr) {
    asm volatile("ldmatrix.sync.aligned.m8n8.x4.shared.b16 {%0,%1,%2,%3}, [%4];"
                 : "=r"(r[0]), "=r"(r[1]), "=r"(r[2]), "=r"(r[3]) : "r"(addr));
}
__device__ __forceinline__ void stm_x4(uint32_t addr, uint32_t r0, uint32_t r1,
                                       uint32_t r2, uint32_t r3) {
    asm volatile("stmatrix.sync.aligned.m8n8.x4.shared.b16 [%0], {%1,%2,%3,%4};"
                 :: "r"(addr), "r"(r0), "r"(r1), "r"(r2), "r"(r3) : "memory");
}
__device__ __forceinline__ void mma16(float* d, const uint32_t* a,
                                      const uint32_t* b) {
    asm volatile(
        "mma.sync.aligned.m16n8k16.row.col.f32.bf16.bf16.f32 "
        "{%0,%1,%2,%3},{%4,%5,%6,%7},{%8,%9},{%0,%1,%2,%3};"
        : "+f"(d[0]), "+f"(d[1]), "+f"(d[2]), "+f"(d[3])
        : "r"(a[0]), "r"(a[1]), "r"(a[2]), "r"(a[3]), "r"(b[0]), "r"(b[1]));
}
__device__ __forceinline__ uint32_t packbf(float lo, float hi) {
    uint32_t r;
    asm("cvt.rn.bf16x2.f32 %0, %1, %2;" : "=r"(r) : "f"(hi), "f"(lo));
    return r;
}
__device__ __forceinline__ void bulk_g2s(uint32_t dst, const void* src,
                                         uint32_t bytes, uint32_t mb) {
    asm volatile(
        "cp.async.bulk.shared::cta.global.mbarrier::complete_tx::bytes "
        "[%0], [%1], %2, [%3];"
        :: "r"(dst), "l"(src), "r"(bytes), "r"(mb) : "memory");
}
#define NAMED_BAR(id) \
    asm volatile("bar.sync %0, 128;" :: "r"(id) : "memory")
#define MBARRIER_INIT(mb, c) \
    asm volatile("mbarrier.init.shared.b64 [%0], %1;" \
                 :: "r"((uint32_t)(mb)), "r"((uint32_t)(c)) : "memory")
#define MBARRIER_EXPECT_TX(mb, n) \
    asm volatile("mbarrier.arrive.expect_tx.shared.b64 _, [%0], %1;" \
                 :: "r"((uint32_t)(mb)), "r"((uint32_t)(n)) : "memory")
#define MBARRIER_ARRIVE(mb) \
    asm volatile("mbarrier.arrive.shared.b64 _, [%0];" \
                 :: "r"((uint32_t)(mb)) : "memory")
#define MBARRIER_WAIT_PARITY(mb, par) do {                                   \
    uint32_t _mb = (uint32_t)(mb), _pa = (uint32_t)(par), _done;             \
    asm volatile("{ .reg .pred p; mbarrier.try_wait.parity.acquire.cta.shared::cta.b64 p, [%1], %2; selp.b32 %0,1,0,p; }" \
                 : "=r"(_done) : "r"(_mb), "r"(_pa) : "memory");             \
    if (!_done) {                                                            \
        asm volatile("{ .reg .pred P1; WL_%=: mbarrier.try_wait.parity.acquire.cta.shared::cta.b64 P1, [%0], %1, 0x989680; @P1 bra.uni WD_%=; bra.uni WL_%=; WD_%=: }" \
                     :: "r"(_mb), "r"(_pa) : "memory");                      \
    } } while (0)

// SMEM layout (bytes). Activation tiles [row][col bf16], 256B rows,
// 16B-granule XOR swizzle: addr(r,c) = r*256 + (((c>>3) ^ (r&7))<<4) + (c&7)*2
#define OFF_E   0            // 16 KB  E (A of GEMM1), 64x128 bf16
#define OFF_H   16384        // 16 KB  H (A of GEMM2), 64x128 bf16
#define OFF_W1  32768        // 32 KB  W1 chunk [n=h128][k=u128]
#define OFF_W2  65536        // 32 KB  W2 chunk [n=u128][k=h128]
#define OFF_B1  98304        // 512 fp32
#define OFF_B2  100352       // 128 fp32
#define OFF_MF1 100864       // full-barrier W1
#define OFF_MF2 100872       // full-barrier W2
#define OFF_MC1 100880       // consumed-barrier W1 (8 warp arrivals)
#define OFF_MC2 100888       // consumed-barrier W2
#define SMEM_TOTAL 100992

__global__ void __launch_bounds__(THREADS, 2)
rk4_kernel(const float* __restrict__ x0, const float* __restrict__ b1g,
           const float* __restrict__ b2g, float* __restrict__ xout) {
    extern __shared__ unsigned char smem[];
    const uint32_t sb = smem_u32(smem);
    float* sB1 = (float*)(smem + OFF_B1);
    float* sB2 = (float*)(smem + OFF_B2);

    const int tid  = threadIdx.x;
    const int lane = tid & 31;
    const int wid  = tid >> 5;     // 0..7
    const int qr   = lane >> 2;
    const int qc   = lane & 3;
    const int wm   = wid >> 2;     // 0..1  M strip (32 rows); warps 0-3 / 4-7
    const int wn   = wid & 3;      // 0..3  N strip (32 cols)
    const int barid = 1 + wm;      // named barrier per wm-group

    if (tid == 0) {
        MBARRIER_INIT(sb + OFF_MF1, 1);
        MBARRIER_INIT(sb + OFF_MF2, 1);
        MBARRIER_INIT(sb + OFF_MC1, 8);
        MBARRIER_INIT(sb + OFF_MC2, 8);
    }
    sB1[tid] = b1g[tid];
    sB1[tid + 256] = b1g[tid + 256];
    if (tid < 128) sB2[tid] = b2g[tid];

    // ---- init: x0 -> xout (fp32 state) and sE (bf16, swizzled) ----
    const float* xg = x0   + (size_t)blockIdx.x * (MROWS * 128);
    float*       xo = xout + (size_t)blockIdx.x * (MROWS * 128);
    for (int i = tid; i < MROWS * 64; i += THREADS) {   // one bf16x2 each
        int r = i >> 6, c = (i & 63) << 1;
        float2 v = *(const float2*)(xg + r * 128 + c);
        *(float2*)(xo + r * 128 + c) = v;
        *(uint32_t*)(smem + OFF_E + r * 256 + (((c >> 3) ^ (r & 7)) << 4) +
                     (c & 7) * 2) = packbf(v.x, v.y);
    }
    __syncthreads();   // mbarriers initialized, sE/biases written

    if (tid == 0) {
        MBARRIER_EXPECT_TX(sb + OFF_MF1, 32768);
        bulk_g2s(sb + OFF_W1, g_w1s, 32768, sb + OFF_MF1);
        MBARRIER_EXPECT_TX(sb + OFF_MF2, 32768);
        bulk_g2s(sb + OFF_W2, g_w2s, 32768, sb + OFF_MF2);
    }

    // ldmatrix lane address components
    const int arow0 = wm * 32 + ((lane >> 3) & 1) * 8 + (lane & 7);  // +mi*16
    const int asel  = lane >> 4;            // k8-half for A
    const int brow0 = ((lane >> 4) << 3) + (lane & 7);               // +pr*16
    const int bsel  = (lane >> 3) & 1;      // k8-half for B

    // stmatrix lane address: matrix g = lane>>3 -> {mi = g>>1, rh = g&1}
    const int srow = wm * 32 + ((lane >> 4) & 1) * 16 + ((lane >> 3) & 1) * 8 +
                     (lane & 7);
    const uint32_t srow_base = (uint32_t)srow * 256;
    const int s7 = srow & 7;

    float acc[32];
    #pragma unroll
    for (int i = 0; i < 32; i++) acc[i] = 0.0f;

    int pf1 = 0, pf2 = 0, pc1 = 0, pc2 = 0;   // mbarrier phase parities

    #pragma unroll 1
    for (int ev = 0; ev < 80; ev++) {
        const int stage = ev & 3;
        const float ws = (stage == 0 || stage == 3) ? 1.0f : 2.0f;
        const float cs = (stage == 2) ? DTS : 0.5f * DTS;

        float out[32];
        #pragma unroll
        for (int i = 0; i < 32; i++) out[i] = 0.0f;

        #pragma unroll 1
        for (int ch = 0; ch < 4; ch++) {
            const bool last = (ev == 79 && ch == 3);

            // wait W1(ch) ready
            MBARRIER_WAIT_PARITY(sb + OFF_MF1, pf1); pf1 ^= 1;

            // ---- GEMM1: h1 = E(64x128) @ W1c^T, warp tile M32 x N32 ----
            float h1[32];
            #pragma unroll
            for (int i = 0; i < 32; i++) h1[i] = 0.0f;
            #pragma unroll
            for (int k16 = 0; k16 < 8; k16++) {
                uint32_t a[2][4], b[2][4];
                #pragma unroll
                for (int mi = 0; mi < 2; mi++) {
                    int r = arow0 + mi * 16;
                    ldm_x4(a[mi], sb + OFF_E + r * 256 +
                                  (((2 * k16 + asel) ^ (r & 7)) << 4));
                }
                #pragma unroll
                for (int pr = 0; pr < 2; pr++) {
                    int n = wn * 32 + pr * 16 + brow0;
                    ldm_x4(b[pr], sb + OFF_W1 + n * 256 +
                                  (((2 * k16 + bsel) ^ (n & 7)) << 4));
                }
                #pragma unroll
                for (int mi = 0; mi < 2; mi++)
                    #pragma unroll
                    for (int pr = 0; pr < 2; pr++)
                        #pragma unroll
                        for (int j = 0; j < 2; j++)
                            mma16(h1 + (mi * 4 + pr * 2 + j) * 4,
                                  a[mi], &b[pr][2 * j]);
            }
            if (lane == 0) MBARRIER_ARRIVE(sb + OFF_MC1);  // W1(ch) consumed

            // ---- epilogue1: bias + relu -> sH via stmatrix.x4 ----
            #pragma unroll
            for (int ni = 0; ni < 4; ni++) {
                const int col = wn * 32 + ni * 8 + 2 * qc;
                const float bb0 = sB1[ch * 128 + col];
                const float bb1 = sB1[ch * 128 + col + 1];
                const int q0 = ni * 4;        // mi = 0
                const int q1 = (4 + ni) * 4;  // mi = 1
                uint32_t m0 = packbf(fmaxf(h1[q0 + 0] + bb0, 0.0f),
                                     fmaxf(h1[q0 + 1] + bb1, 0.0f));
                uint32_t m1 = packbf(fmaxf(h1[q0 + 2] + bb0, 0.0f),
                                     fmaxf(h1[q0 + 3] + bb1, 0.0f));
                uint32_t m2 = packbf(fmaxf(h1[q1 + 0] + bb0, 0.0f),
                                     fmaxf(h1[q1 + 1] + bb1, 0.0f));
                uint32_t m3 = packbf(fmaxf(h1[q1 + 2] + bb0, 0.0f),
                                     fmaxf(h1[q1 + 3] + bb1, 0.0f));
                const int g8 = wn * 4 + ni;
                stm_x4(sb + OFF_H + srow_base + ((g8 ^ s7) << 4),
                       m0, m1, m2, m3);
            }
            NAMED_BAR(barid);   // H strip visible within wm-group

            // reissue W1(next chunk) once all 8 warps consumed it
            if (!last) {
                if (tid == 0) {
                    MBARRIER_WAIT_PARITY(sb + OFF_MC1, pc1);
                    MBARRIER_EXPECT_TX(sb + OFF_MF1, 32768);
                    bulk_g2s(sb + OFF_W1,
                             (const char*)g_w1s + ((ch + 1) & 3) * 32768,
                             32768, sb + OFF_MF1);
                }
                pc1 ^= 1;
            }

            // wait W2(ch) ready
            MBARRIER_WAIT_PARITY(sb + OFF_MF2, pf2); pf2 ^= 1;

            // ---- GEMM2: out += H(64x128) @ W2c^T, warp tile M32 x N32 ----
            #pragma unroll
            for (int k16 = 0; k16 < 8; k16++) {
                uint32_t a[2][4], b[2][4];
                #pragma unroll
                for (int mi = 0; mi < 2; mi++) {
                    int r = arow0 + mi * 16;
                    ldm_x4(a[mi], sb + OFF_H + r * 256 +
                                  (((2 * k16 + asel) ^ (r & 7)) << 4));
                }
                #pragma unroll
                for (int pr = 0; pr < 2; pr++) {
                    int n = wn * 32 + pr * 16 + brow0;
                    ldm_x4(b[pr], sb + OFF_W2 + n * 256 +
                                  (((2 * k16 + bsel) ^ (n & 7)) << 4));
                }
                #pragma unroll
                for (int mi = 0; mi < 2; mi++)
                    #pragma unroll
                    for (int pr = 0; pr < 2; pr++)
                        #pragma unroll
                        for (int j = 0; j < 2; j++)
                            mma16(out + (mi * 4 + pr * 2 + j) * 4,
                                  a[mi], &b[pr][2 * j]);
            }
            if (lane == 0) MBARRIER_ARRIVE(sb + OFF_MC2);  // W2(ch) consumed
            if (ch < 3) NAMED_BAR(barid);  // H free for next epilogue1
            // (ch==3: next H write is after the RK4-epilogue barrier)

            // reissue W2(next chunk)
            if (!last) {
                if (tid == 0) {
                    MBARRIER_WAIT_PARITY(sb + OFF_MC2, pc2);
                    MBARRIER_EXPECT_TX(sb + OFF_MF2, 32768);
                    bulk_g2s(sb + OFF_W2,
                             (const char*)g_w2s + ((ch + 1) & 3) * 32768,
                             32768, sb + OFF_MF2);
                }
                pc2 ^= 1;
            }
        }  // chunks

        // ---- RK4 stage epilogue (x in xout; E written via stmatrix) ----
        #pragma unroll
        for (int ni = 0; ni < 4; ni++) {
            const int col = wn * 32 + ni * 8 + 2 * qc;
            const float b2v0 = sB2[col], b2v1 = sB2[col + 1];
            uint32_t m[4];
            #pragma unroll
            for (int mi = 0; mi < 2; mi++) {
                const int q   = (mi * 4 + ni) * 4;
                const int row = wm * 32 + mi * 16 + qr;
                float2* xp0 = (float2*)(xo + row * 128 + col);
                float2* xp1 = (float2*)(xo + (row + 8) * 128 + col);
                float2 xv0 = *xp0, xv1 = *xp1;
                float k0 = out[q + 0] + b2v0;
                float k1 = out[q + 1] + b2v1;
                float k2 = out[q + 2] + b2v0;
                float k3 = out[q + 3] + b2v1;
                acc[q + 0] += ws * k0; acc[q + 1] += ws * k1;
                acc[q + 2] += ws * k2; acc[q + 3] += ws * k3;
                if (stage < 3) {
                    m[mi * 2 + 0] = packbf(xv0.x + cs * k0, xv0.y + cs * k1);
                    m[mi * 2 + 1] = packbf(xv1.x + cs * k2, xv1.y + cs * k3);
                } else {
                    float n0 = xv0.x + (DTS / 6.0f) * acc[q + 0];
                    float n1 = xv0.y + (DTS / 6.0f) * acc[q + 1];
                    float n2 = xv1.x + (DTS / 6.0f) * acc[q + 2];
                    float n3 = xv1.y + (DTS / 6.0f) * acc[q + 3];
                    *xp0 = make_float2(n0, n1);
                    *xp1 = make_float2(n2, n3);
                    acc[q + 0] = acc[q + 1] = acc[q + 2] = acc[q + 3] = 0.0f;
                    m[mi * 2 + 0] = packbf(n0, n1);
                    m[mi * 2 + 1] = packbf(n2, n3);
                }
            }
            const int g8 = wn * 4 + ni;
            stm_x4(sb + OFF_E + srow_base + ((g8 ^ s7) << 4),
                   m[0], m[1], m[2], m[3]);
        }
        NAMED_BAR(barid);   // E strip visible before next eval's GEMM1
    }  // evals
}

extern "C" void kernel_launch(void* const* d_in, const int* in_sizes, int n_in,
                              void* d_out, int out_size) {
    const float* x0 = (const float*)d_in[0];
    const float* W1 = (const float*)d_in[1];
    const float* b1 = (const float*)d_in[2];
    const float* W2 = (const float*)d_in[3];
    const float* b2 = (const float*)d_in[4];
    float* out = (float*)d_out;

    static bool configured = false;
    if (!configured) {
        cudaFuncSetAttribute(rk4_kernel,
                             cudaFuncAttributeMaxDynamicSharedMemorySize,
                             SMEM_TOTAL);
        configured = true;
    }

    prep_kernel<<<64, 256>>>(W1, W2);
    rk4_kernel<<<65536 / MROWS, THREADS, SMEM_TOTAL>>>(x0, b1, b2, out);
}